// round 2
// baseline (speedup 1.0000x reference)
#include <cuda_runtime.h>
#include <cuda_bf16.h>
#include <math.h>
#include <stdint.h>

typedef unsigned long long ULL;
typedef unsigned int u32;

#define H 40
#define W 40
#define CIN 2048
#define CMID 256
#define NPIX 1600
#define NANCH 8000
#define MAXDET 300

__device__ __constant__ float c_anchor[5] = {32.f, 64.f, 128.f, 256.f, 512.f};

// ---------------- device scratch (static; no allocation) ----------------
__device__ float  g_partial[9 * NPIX * CMID];   // per-tap conv partials
__device__ float  g_x[NPIX * CMID];             // conv+bias+relu output
__device__ float  g_scores[NANCH];
__device__ float4 g_boxes[NANCH];
__device__ float4 g_boxes_sorted[NANCH];
__device__ float  g_rois[MAXDET * 4];
__device__ int    g_kcnt;

// =====================================================================
// Kernel 1: tap-split implicit GEMM.  grid (25, 2, 9), 256 threads.
// Block tile 64 pixels x 128 couts, per-thread 4x8, packed f32x2 FMA.
// =====================================================================
__global__ __launch_bounds__(256, 2) void conv3x3_partial(
    const float* __restrict__ feat, const float* __restrict__ w)
{
    const int mt = blockIdx.x, nt = blockIdx.y, tap = blockIdx.z;
    const int dy = tap / 3 - 1, dx = tap % 3 - 1;
    const int m0 = mt * 64, n0 = nt * 128;
    const int tid = threadIdx.x;

    __shared__ float As[16][68];    // [k][pixel], stride 68 (16B-aligned rows, conflict-free STS)
    __shared__ float Bs[16][132];   // [k][cout], stride 132 (16B-aligned rows)

    // A loader mapping: 64 pixels x 16 k per chunk = 1024 floats; 1 float4/thread
    const int pl = tid >> 2, q = tid & 3;     // pixel-in-tile, k-quarter
    const int p = m0 + pl;
    const int py = p / W, px = p - py * W;
    const int sy = py + dy, sx = px + dx;
    const bool valid = (sx >= 0) && (sx < W) && (sy >= 0) && (sy < H);
    const float* aptr = feat + ((size_t)(valid ? (sy * W + sx) : 0) * CIN + q * 4);

    // B loader mapping: 16 k x 128 n per chunk = 2048 floats; 2 float4/thread
    const int kr = tid >> 4, seg = tid & 15;
    const float* bptr = w + ((size_t)(tap * CIN + kr) * CMID + n0 + seg * 8);

    // compute mapping
    const int mg = tid >> 4, ng = tid & 15;   // m-group (4 rows), n-group (4+4 cols)

    ULL acc[4][4];
#pragma unroll
    for (int i = 0; i < 4; i++)
#pragma unroll
        for (int j = 0; j < 4; j++) acc[i][j] = 0ull;

    for (int c0 = 0; c0 < CIN; c0 += 16) {
        float4 ra = valid ? *(const float4*)aptr : make_float4(0.f, 0.f, 0.f, 0.f);
        float4 rb0 = *(const float4*)bptr;
        float4 rb1 = *(const float4*)(bptr + 4);
        __syncthreads();
        As[q * 4 + 0][pl] = ra.x;
        As[q * 4 + 1][pl] = ra.y;
        As[q * 4 + 2][pl] = ra.z;
        As[q * 4 + 3][pl] = ra.w;
        *(float4*)&Bs[kr][seg * 8]     = rb0;
        *(float4*)&Bs[kr][seg * 8 + 4] = rb1;
        __syncthreads();
        aptr += 16;
        bptr += (size_t)16 * CMID;

#pragma unroll
        for (int kc = 0; kc < 16; kc++) {
            float4 av = *(const float4*)&As[kc][mg * 4];
            float4 b0 = *(const float4*)&Bs[kc][ng * 4];
            float4 b1 = *(const float4*)&Bs[kc][64 + ng * 4];
            ULL bp[4];
            {
                u32 x0 = __float_as_uint(b0.x), x1 = __float_as_uint(b0.y);
                u32 x2 = __float_as_uint(b0.z), x3 = __float_as_uint(b0.w);
                u32 x4 = __float_as_uint(b1.x), x5 = __float_as_uint(b1.y);
                u32 x6 = __float_as_uint(b1.z), x7 = __float_as_uint(b1.w);
                asm("mov.b64 %0, {%1, %2};" : "=l"(bp[0]) : "r"(x0), "r"(x1));
                asm("mov.b64 %0, {%1, %2};" : "=l"(bp[1]) : "r"(x2), "r"(x3));
                asm("mov.b64 %0, {%1, %2};" : "=l"(bp[2]) : "r"(x4), "r"(x5));
                asm("mov.b64 %0, {%1, %2};" : "=l"(bp[3]) : "r"(x6), "r"(x7));
            }
            float am[4] = {av.x, av.y, av.z, av.w};
#pragma unroll
            for (int mm = 0; mm < 4; mm++) {
                u32 au = __float_as_uint(am[mm]);
                ULL a2;
                asm("mov.b64 %0, {%1, %1};" : "=l"(a2) : "r"(au));
#pragma unroll
                for (int qq = 0; qq < 4; qq++)
                    asm("fma.rn.f32x2 %0, %1, %2, %0;" : "+l"(acc[mm][qq]) : "l"(a2), "l"(bp[qq]));
            }
        }
    }

    // store partials (each ULL = 2 consecutive fp32)
#pragma unroll
    for (int mm = 0; mm < 4; mm++) {
        int mrow = m0 + mg * 4 + mm;
        size_t base = ((size_t)tap * NPIX + mrow) * CMID + n0;
        *(ULL*)&g_partial[base + ng * 4 + 0]      = acc[mm][0];
        *(ULL*)&g_partial[base + ng * 4 + 2]      = acc[mm][1];
        *(ULL*)&g_partial[base + 64 + ng * 4 + 0] = acc[mm][2];
        *(ULL*)&g_partial[base + 64 + ng * 4 + 2] = acc[mm][3];
    }
}

// =====================================================================
// Kernel 2: fixed-order tap reduce + bias + relu.  grid 1600, 256 thr.
// =====================================================================
__global__ void reduce_taps(const float* __restrict__ conv_b)
{
    const int m = blockIdx.x, n = threadIdx.x;
    float s = conv_b[n];
#pragma unroll
    for (int t = 0; t < 9; t++)
        s += g_partial[((size_t)t * NPIX + m) * CMID + n];
    g_x[(size_t)m * CMID + n] = fmaxf(s, 0.f);
}

// =====================================================================
// Kernel 3: 1x1 heads + score + anchor decode. grid 1600, 256 thr.
// =====================================================================
__global__ void heads_decode(
    const float* __restrict__ cls_w, const float* __restrict__ cls_b,
    const float* __restrict__ reg_w, const float* __restrict__ reg_b)
{
    const int p = blockIdx.x;
    const int tid = threadIdx.x;
    const int wid = tid >> 5, lid = tid & 31;
    __shared__ float xs[256];
    __shared__ float ob[32];

    xs[tid] = g_x[(size_t)p * CMID + tid];
    __syncthreads();

    // 30 outputs (10 cls + 20 reg), warp-per-output
    for (int o = wid; o < 30; o += 8) {
        const float* wm;
        int ld, col;
        float bias;
        if (o < 10) { wm = cls_w; ld = 10; col = o;      bias = cls_b[o]; }
        else        { wm = reg_w; ld = 20; col = o - 10; bias = reg_b[o - 10]; }
        float s = 0.f;
        for (int k = lid; k < 256; k += 32)
            s += xs[k] * wm[(size_t)k * ld + col];
#pragma unroll
        for (int off = 16; off > 0; off >>= 1)
            s += __shfl_xor_sync(0xFFFFFFFFu, s, off);
        if (lid == 0) ob[o] = s + bias;
    }
    __syncthreads();

    if (tid < 5) {
        const int a = tid;
        float l0 = ob[2 * a], l1 = ob[2 * a + 1];
        float score = 1.f / (1.f + expf(l0 - l1));
        float d0 = ob[10 + 4 * a + 0];
        float d1 = ob[10 + 4 * a + 1];
        float d2 = ob[10 + 4 * a + 2];
        float d3 = ob[10 + 4 * a + 3];
        float px = (float)(p % W), py = (float)(p / W);
        float base = c_anchor[a];
        float bw = expf(d2) * base;
        float bh = expf(d3) * base;
        float xc = px + d0, yc = py + d1;
        g_scores[p * 5 + a] = score;
        g_boxes[p * 5 + a] = make_float4(xc - 0.5f * bw, yc - 0.5f * bh,
                                         xc + 0.5f * bw, yc + 0.5f * bh);
    }
}

// =====================================================================
// Kernel 4: stable descending bitonic sort of 8192 (8000 + pad).
// key = (score_bits << 32) | (~index)  -> desc score, asc index.
// Single block, 256 threads, 64KB dynamic smem.
// =====================================================================
__global__ void sort_scores()
{
    extern __shared__ ULL sk[];
    const int tid = threadIdx.x;

    for (int i = tid; i < 8192; i += 256) {
        if (i < NANCH) {
            u32 sb = __float_as_uint(g_scores[i]);   // scores in (0,1): positive, order-preserving bits
            sk[i] = ((ULL)sb << 32) | (ULL)(0xFFFFFFFFu - (u32)i);
        } else {
            sk[i] = 0ull;   // pads sort last
        }
    }
    __syncthreads();

    for (int k = 2; k <= 8192; k <<= 1) {
        for (int j = k >> 1; j > 0; j >>= 1) {
            for (int t = tid; t < 4096; t += 256) {
                int i = ((t & ~(j - 1)) << 1) | (t & (j - 1));
                int l = i | j;
                bool desc = ((i & k) == 0);
                ULL a = sk[i], b = sk[l];
                if (desc ? (a < b) : (a > b)) { sk[i] = b; sk[l] = a; }
            }
            __syncthreads();
        }
    }

    for (int i = tid; i < NANCH; i += 256) {
        u32 idx = 0xFFFFFFFFu - (u32)(sk[i] & 0xFFFFFFFFull);
        g_boxes_sorted[i] = g_boxes[idx];
    }
}

// =====================================================================
// Kernel 5: exact greedy NMS (thr 0.7), single block, 256 threads.
// =====================================================================
__global__ void nms_kernel()
{
    const int tid = threadIdx.x;
    __shared__ u32 alive[250];          // 250*32 = 8000 bits
    __shared__ int s_next, s_cur, s_kcnt;
    __shared__ float4 s_box;

    if (tid < 250) alive[tid] = 0xFFFFFFFFu;
    if (tid == 0) { s_cur = 0; s_kcnt = 0; }
    __syncthreads();

    while (true) {
        if (tid == 0) {
            int nx = -1;
            int sw = s_cur >> 5;
            for (int wd = sw; wd < 250; wd++) {
                u32 m = alive[wd];
                if (wd == sw) m &= ~((s_cur & 31) ? ((1u << (s_cur & 31)) - 1u) : 0u);
                if (m) { nx = wd * 32 + __ffs(m) - 1; break; }
            }
            if (nx >= 0 && s_kcnt < MAXDET) {
                float4 b = g_boxes_sorted[nx];
                s_box = b;
                g_rois[s_kcnt * 4 + 0] = b.x;
                g_rois[s_kcnt * 4 + 1] = b.y;
                g_rois[s_kcnt * 4 + 2] = b.z;
                g_rois[s_kcnt * 4 + 3] = b.w;
                s_kcnt++;
                s_cur = nx + 1;
                s_next = nx;
            } else {
                s_next = -1;
            }
        }
        __syncthreads();
        int nx = s_next;
        if (nx < 0) break;

        float4 kb = s_box;
        float areaK = (kb.z - kb.x) * (kb.w - kb.y);

        if (tid < 250) {
            int base = tid * 32;
            u32 mask;
            if (base > nx)            mask = 0xFFFFFFFFu;
            else if (base + 31 <= nx) mask = 0u;
            else                      mask = ~((1u << (nx - base + 1)) - 1u);
            u32 cand = alive[tid] & mask;
            u32 kill = 0;
            while (cand) {
                int b = __ffs(cand) - 1;
                cand &= cand - 1;
                float4 bb = g_boxes_sorted[base + b];
                float iw = fminf(kb.z, bb.z) - fmaxf(kb.x, bb.x);
                float ih = fminf(kb.w, bb.w) - fmaxf(kb.y, bb.y);
                iw = fmaxf(iw, 0.f); ih = fmaxf(ih, 0.f);
                float inter = iw * ih;
                float areaB = (bb.z - bb.x) * (bb.w - bb.y);
                float iou = __fdiv_rn(inter, areaK + areaB - inter);
                if (iou >= 0.7f) kill |= (1u << b);
            }
            if (kill) alive[tid] &= ~kill;
        }
        __syncthreads();
    }

    // zero remaining roi rows
    int kc = s_kcnt;
    if (tid == 0) g_kcnt = kc;
    int rem = (MAXDET - kc) * 4;
    for (int e = tid; e < rem; e += 256) g_rois[kc * 4 + e] = 0.f;
}

// =====================================================================
// Kernel 6: FC head + softmax + output. grid 300, 128 threads.
// out layout: [class_scores 300x4 | box_deltas 300x4 | rois 300x4]
// =====================================================================
__global__ void fc_head(
    const float* __restrict__ fc1_w, const float* __restrict__ fc1_b,
    const float* __restrict__ clsh_w, const float* __restrict__ clsh_b,
    const float* __restrict__ regh_w, const float* __restrict__ regh_b,
    float* __restrict__ out)
{
    const int r = blockIdx.x;
    const int tid = threadIdx.x;
    __shared__ float s_roi[4];
    __shared__ float red[8][128];

    if (tid < 4) s_roi[tid] = g_rois[r * 4 + tid];
    __syncthreads();
    float r0 = s_roi[0], r1 = s_roi[1], r2 = s_roi[2], r3 = s_roi[3];

    float cls[4] = {0.f, 0.f, 0.f, 0.f};
    float reg[4] = {0.f, 0.f, 0.f, 0.f};
    for (int j = tid; j < 1024; j += 128) {
        float fc = r0 * fc1_w[j] + r1 * fc1_w[1024 + j]
                 + r2 * fc1_w[2048 + j] + r3 * fc1_w[3072 + j] + fc1_b[j];
        fc = fmaxf(fc, 0.f);
#pragma unroll
        for (int c = 0; c < 4; c++) {
            cls[c] += fc * clsh_w[j * 4 + c];
            reg[c] += fc * regh_w[j * 4 + c];
        }
    }
#pragma unroll
    for (int c = 0; c < 4; c++) { red[c][tid] = cls[c]; red[4 + c][tid] = reg[c]; }
    __syncthreads();
    for (int s = 64; s > 0; s >>= 1) {
        if (tid < s) {
#pragma unroll
            for (int c = 0; c < 8; c++) red[c][tid] += red[c][tid + s];
        }
        __syncthreads();
    }
    if (tid == 0) {
        float lg[4], mx = -1e30f;
#pragma unroll
        for (int c = 0; c < 4; c++) { lg[c] = red[c][0] + clsh_b[c]; mx = fmaxf(mx, lg[c]); }
        float es[4], sum = 0.f;
#pragma unroll
        for (int c = 0; c < 4; c++) { es[c] = expf(lg[c] - mx); sum += es[c]; }
#pragma unroll
        for (int c = 0; c < 4; c++) {
            out[r * 4 + c]              = es[c] / sum;                 // class_scores
            out[1200 + r * 4 + c]       = red[4 + c][0] + regh_b[c];   // box_deltas
            out[2400 + r * 4 + c]       = s_roi[c];                    // rois
        }
    }
}

// =====================================================================
extern "C" void kernel_launch(void* const* d_in, const int* in_sizes, int n_in,
                              void* d_out, int out_size)
{
    const float* feat   = (const float*)d_in[0];
    const float* conv_w = (const float*)d_in[1];
    const float* conv_b = (const float*)d_in[2];
    const float* cls_w  = (const float*)d_in[3];
    const float* cls_b  = (const float*)d_in[4];
    const float* reg_w  = (const float*)d_in[5];
    const float* reg_b  = (const float*)d_in[6];
    const float* fc1_w  = (const float*)d_in[7];
    const float* fc1_b  = (const float*)d_in[8];
    const float* clsh_w = (const float*)d_in[9];
    const float* clsh_b = (const float*)d_in[10];
    const float* regh_w = (const float*)d_in[11];
    const float* regh_b = (const float*)d_in[12];
    float* out = (float*)d_out;

    cudaFuncSetAttribute(sort_scores, cudaFuncAttributeMaxDynamicSharedMemorySize, 65536);

    conv3x3_partial<<<dim3(25, 2, 9), 256>>>(feat, conv_w);
    reduce_taps<<<NPIX, 256>>>(conv_b);
    heads_decode<<<NPIX, 256>>>(cls_w, cls_b, reg_w, reg_b);
    sort_scores<<<1, 256, 65536>>>();
    nms_kernel<<<1, 256>>>();
    fc_head<<<MAXDET, 128>>>(fc1_w, fc1_b, clsh_w, clsh_b, regh_w, regh_b, out);
}